// round 10
// baseline (speedup 1.0000x reference)
#include <cuda_runtime.h>
#include <stdint.h>

// Problem constants (fixed by the dataset)
#define NLAT_IN  181
#define NLON_IN  360
#define NLON_X   720                     // wrap-free duplicated width
#define NLAT_OUT 91
#define NLON_OUT 180
#define KS       9
#define B_       4
#define CIN      32
#define COUT     32
#define BC       128
#define CK       288                     // CIN*KS

#define WT       10                      // longitudes per unit (10 warps)
#define NWTILES  (NLON_OUT / WT)         // 18
#define NUNITS   (NLAT_OUT * NWTILES)    // 1638

#define MAX_NNZ   (1 << 21)
#define NCELL     (9 * NLON_IN)          // 3240 (rr, lon) cells per output lat
#define RECF      12                     // floats per record: psi[0..8], hdr, pad, pad

// ---------------- device scratch (no cudaMalloc allowed) ----------------
__device__ float    g_xqt[NLAT_IN * NLON_X * BC];        // 66.8 MB (wrap-free)
__device__ float    g_wt[CK * COUT];                     // W transposed [ck][o]
__device__ int2     g_ent[MAX_NNZ];                      // (k<<12|cell, psi_bits)
__device__ int      g_he[NLAT_OUT + 1];                  // per-h entry ranges
__device__ float    g_psi[(NLAT_OUT * NCELL + 4) * RECF]; // records (hdr fused)
__device__ int      g_npix[NLAT_OUT];
__device__ int      g_work;                              // dynamic unit counter

// ---------------- 1) decode entries + per-h ranges (+ counter reset) ----------------
// dtype: word pidx32[2*nnz-1] is h_last=90 (int32) or high half of flat (=0, int64)
__global__ void decode_kernel(const int* __restrict__ pidx,
                              const float* __restrict__ pvals, int nnz) {
    int e = blockIdx.x * blockDim.x + threadIdx.x;
    if (e == 0) g_work = 0;                          // reset stealing counter each replay
    if (e >= nnz || e >= MAX_NNZ) return;
    int is64 = (pidx[2 * nnz - 1] == 0) ? 1 : 0;
    int k, h, flat, hp = -1;
    if (is64) {
        const long long* p = (const long long*)pidx;
        k = (int)p[e]; h = (int)p[(long long)nnz + e]; flat = (int)p[2LL * nnz + e];
        if (e > 0) hp = (int)p[(long long)nnz + e - 1];
    } else {
        k = pidx[e]; h = pidx[nnz + e]; flat = pidx[2 * nnz + e];
        if (e > 0) hp = pidx[nnz + e - 1];
    }
    int row = flat / NLON_IN;
    int lon = flat - row * NLON_IN;
    int row0 = 2 * h - 4; if (row0 < 0) row0 = 0;
    int rr = row - row0;
    rr = rr < 0 ? 0 : (rr > 8 ? 8 : rr);             // safety clamp (data guarantees 0..8)
    int2 ent;
    ent.x = ((k & 15) << 12) | (rr * NLON_IN + lon);
    ent.y = __float_as_int(pvals[e]);
    g_ent[e] = ent;

    for (int t = hp + 1; t <= h; t++) g_he[t] = e;   // h is ascending
    if (e == nnz - 1)
        for (int t = h + 1; t <= NLAT_OUT; t++) g_he[t] = nnz;
}

// ---------------- 2) per-h build: count -> scan -> zero -> scatter ----------------
__global__ void __launch_bounds__(1024) build_kernel() {
    __shared__ int s_cnt[NCELL];                     // 12.96 KB (count -> slot map)
    __shared__ int s_wf[32];
    __shared__ int s_pixb;
    int h = blockIdx.x;
    int t = threadIdx.x, lane = t & 31, wid = t >> 5;
    int row0 = 2 * h - 4; if (row0 < 0) row0 = 0;

    for (int c = t; c < NCELL; c += 1024) s_cnt[c] = 0;
    if (t == 0) s_pixb = 0;
    __syncthreads();

    int e0 = g_he[h], e1 = g_he[h + 1];
    for (int e = e0 + t; e < e1; e += 1024)
        atomicAdd(&s_cnt[g_ent[e].x & 4095], 1);
    __syncthreads();

    float* psi = g_psi + (size_t)h * NCELL * RECF;

    // chunked block scan over 3240 cells: compact slot ids
    for (int c0 = 0; c0 < NCELL; c0 += 1024) {
        int cell = c0 + t;
        int flag = (cell < NCELL && s_cnt[cell] > 0) ? 1 : 0;
        int sf = flag;
        #pragma unroll
        for (int o = 1; o < 32; o <<= 1) {
            int vf = __shfl_up_sync(~0u, sf, o);
            if (lane >= o) sf += vf;
        }
        if (lane == 31) s_wf[wid] = sf;
        __syncthreads();
        if (wid == 0) {
            int wf = s_wf[lane];
            #pragma unroll
            for (int o = 1; o < 32; o <<= 1) {
                int vf = __shfl_up_sync(~0u, wf, o);
                if (lane >= o) wf += vf;
            }
            s_wf[lane] = wf;
        }
        __syncthreads();
        int exf = sf - flag + ((wid > 0) ? s_wf[wid - 1] : 0);
        int pixb = s_pixb;
        if (flag) s_cnt[cell] = pixb + exf;          // slot map
        __syncthreads();
        if (t == 0) s_pixb += s_wf[31];
        __syncthreads();
    }
    int np = s_pixb;
    if (t == 0) g_npix[h] = np;

    // zero np+1 records (pad record => pipeline can prefetch past the end)
    for (int i = t; i < (np + 1) * RECF; i += 1024) psi[i] = 0.f;
    __syncthreads();

    // scatter psi + fused 720-header (idempotent) into dense records
    for (int e = e0 + t; e < e1; e += 1024) {
        int2 ent = g_ent[e];
        int cell = ent.x & 4095;
        int k    = (ent.x >> 12) & 15;
        int slot = s_cnt[cell];
        psi[slot * RECF + k] = __int_as_float(ent.y);
        int rr  = cell / NLON_IN;
        int lon = cell - rr * NLON_IN;
        psi[slot * RECF + 9] =
            __uint_as_float((uint32_t)((row0 + rr) * NLON_X + lon));
    }
}

// ---------------- 3) fused xq-transpose (720-wide) + W-transpose ----------------
__global__ void __launch_bounds__(256) xqwt_kernel(const float* __restrict__ x,
                                                   const float* __restrict__ qw,
                                                   const float* __restrict__ w) {
    int bi = blockIdx.x;
    if (bi < 8688) {
        __shared__ float tile[32][33];
        int g0 = bi % 12, g1 = (bi / 12) % 4, row = bi / 48;
        int lon0 = g0 * 32, bc0 = g1 * 32;
        int tx = threadIdx.x & 31, ty = threadIdx.x >> 5;   // 32 x 8
        float q = qw[row];
        for (int i = ty; i < 32; i += 8) {
            int lon = lon0 + tx;
            float v = 0.f;
            if (lon < NLON_IN)
                v = x[((size_t)(bc0 + i) * NLAT_IN + row) * NLON_IN + lon];
            tile[i][tx] = v * q;
        }
        __syncthreads();
        for (int i = ty; i < 32; i += 8) {
            int lon = lon0 + i;
            if (lon < NLON_IN) {
                float v = tile[tx][i];
                size_t base = (size_t)row * NLON_X * BC;
                g_xqt[base + (size_t)lon * BC + bc0 + tx] = v;
                g_xqt[base + (size_t)(lon + NLON_IN) * BC + bc0 + tx] = v;
            }
        }
    } else {
        int id = (bi - 8688) * 256 + threadIdx.x;
        if (id < COUT * CK) {
            int o = id / CK;
            int ck = id - o * CK;
            g_wt[ck * COUT + o] = w[id];
        }
    }
}

// ---------------- 4) persistent fused conv: work-stealing units ----------------
__global__ void __launch_bounds__(WT * 32) conv_kernel(const float* __restrict__ bias,
                                                       float* __restrict__ out) {
    __shared__ float s_acc[WT * 4 * 289];            // 46.2 KB
    __shared__ int s_u;

    int lane = threadIdx.x & 31;
    int warp = threadIdx.x >> 5;
    int vbase = lane * 4;
    int boff = lane >> 3;
    int c0 = (lane & 7) * 4;

    for (;;) {
        if (threadIdx.x == 0) s_u = atomicAdd(&g_work, 1);
        __syncthreads();
        int u = s_u;
        if (u >= NUNITS) break;

        int uh = u / NWTILES;
        int wt = u - uh * NWTILES;
        int h  = (uh & 1) ? (90 - (uh >> 1)) : (uh >> 1);   // heavy polar rows first
        int w  = wt * WT + warp;
        int tw = 2 * w;

        int np = g_npix[h];
        const float4* __restrict__ rec = (const float4*)(g_psi + (size_t)h * NCELL * RECF);

        float y[4][KS];
        #pragma unroll
        for (int ci = 0; ci < 4; ci++)
            #pragma unroll
            for (int k = 0; k < KS; k++) y[ci][k] = 0.f;

        if (np > 0) {
            float4 q0 = __ldg(&rec[0]);
            float4 q1 = __ldg(&rec[1]);
            float4 q2 = __ldg(&rec[2]);
            uint32_t off = __float_as_uint(q2.y) + (uint32_t)tw;
            float4 v = __ldg((const float4*)&g_xqt[((size_t)off << 7) + vbase]);

            #pragma unroll 2
            for (int p = 0; p < np; p++) {
                float4 nq0 = __ldg(&rec[(p + 1) * 3 + 0]);
                float4 nq1 = __ldg(&rec[(p + 1) * 3 + 1]);
                float4 nq2 = __ldg(&rec[(p + 1) * 3 + 2]);
                uint32_t noff = __float_as_uint(nq2.y) + (uint32_t)tw;
                float4 nv = __ldg((const float4*)&g_xqt[((size_t)noff << 7) + vbase]);

                float vv[4] = {v.x, v.y, v.z, v.w};
                #pragma unroll
                for (int ci = 0; ci < 4; ci++) {
                    y[ci][0] = fmaf(q0.x, vv[ci], y[ci][0]);
                    y[ci][1] = fmaf(q0.y, vv[ci], y[ci][1]);
                    y[ci][2] = fmaf(q0.z, vv[ci], y[ci][2]);
                    y[ci][3] = fmaf(q0.w, vv[ci], y[ci][3]);
                    y[ci][4] = fmaf(q1.x, vv[ci], y[ci][4]);
                    y[ci][5] = fmaf(q1.y, vv[ci], y[ci][5]);
                    y[ci][6] = fmaf(q1.z, vv[ci], y[ci][6]);
                    y[ci][7] = fmaf(q1.w, vv[ci], y[ci][7]);
                    y[ci][8] = fmaf(q2.x, vv[ci], y[ci][8]);
                }
                q0 = nq0; q1 = nq1; q2 = nq2; v = nv;
            }
        }

        // stage-1 result -> smem [wslot*4+b][c*9+k]
        int sb = (warp * 4 + boff) * 289 + c0 * KS;
        #pragma unroll
        for (int ci = 0; ci < 4; ci++)
            #pragma unroll
            for (int k = 0; k < KS; k++)
                s_acc[sb + ci * KS + k] = y[ci][k];
        __syncthreads();

        // stage 2: out[b,o,h,w] = sum_ck W[o][ck] * y[b][ck] ; lane = o
        float r0 = 0.f, r1 = 0.f, r2 = 0.f, r3 = 0.f;
        int slot0 = warp * 4;
        const float* s0 = &s_acc[(slot0 + 0) * 289];
        const float* s1 = &s_acc[(slot0 + 1) * 289];
        const float* s2 = &s_acc[(slot0 + 2) * 289];
        const float* s3 = &s_acc[(slot0 + 3) * 289];
        #pragma unroll 4
        for (int ck = 0; ck < CK; ck++) {
            float wv = g_wt[ck * COUT + lane];
            r0 = fmaf(wv, s0[ck], r0);
            r1 = fmaf(wv, s1[ck], r1);
            r2 = fmaf(wv, s2[ck], r2);
            r3 = fmaf(wv, s3[ck], r3);
        }
        float bo = bias[lane];
        float rr[4] = {r0, r1, r2, r3};
        #pragma unroll
        for (int p = 0; p < 4; p++) {
            int slot = slot0 + p;
            int wp = slot >> 2;
            int bp = slot & 3;
            out[(((size_t)(bp * COUT + lane)) * NLAT_OUT + h) * NLON_OUT + (wt * WT + wp)]
                = rr[p] + bo;
        }
        __syncthreads();   // protect s_acc / s_u before next unit
    }
}

// ---------------- launch ----------------
extern "C" void kernel_launch(void* const* d_in, const int* in_sizes, int n_in,
                              void* d_out, int out_size) {
    const float* x      = (const float*)d_in[0];
    const float* qw     = (const float*)d_in[1];
    const float* pvals  = (const float*)d_in[2];
    const float* weight = (const float*)d_in[3];
    const float* bias   = (const float*)d_in[4];
    const int*   pidx   = (const int*)d_in[5];
    float* out = (float*)d_out;

    int nnz = in_sizes[2];

    cudaFuncSetAttribute(conv_kernel,
                         cudaFuncAttributePreferredSharedMemoryCarveout,
                         cudaSharedmemCarveoutMaxShared);

    decode_kernel<<<(nnz + 255) / 256, 256>>>(pidx, pvals, nnz);        // launch 1
    build_kernel<<<NLAT_OUT, 1024>>>();                                 // launch 2
    xqwt_kernel<<<8724, 256>>>(x, qw, weight);                          // launch 3
    conv_kernel<<<444, WT * 32>>>(bias, out);                           // launch 4 (profiled)
}

// round 11
// speedup vs baseline: 1.5023x; 1.5023x over previous
#include <cuda_runtime.h>
#include <stdint.h>

// Problem constants (fixed by the dataset)
#define NLAT_IN  181
#define NLON_IN  360
#define NLAT_OUT 91
#define NLON_OUT 180
#define KS       9
#define B_       4
#define CIN      32
#define COUT     32
#define BC       128
#define CK       288                     // CIN*KS

#define WT       5                       // longitudes per block (5 w x 2 chalf = 10 warps)
#define NWTILES  (NLON_OUT / WT)         // 36

#define MAX_NNZ   (1 << 21)
#define NCELL     (9 * NLON_IN)          // 3240 (rr, lon) cells per output lat
#define RECF      12                     // floats per record: psi[0..8], hdr, pad, pad

// ---------------- device scratch (no cudaMalloc allowed) ----------------
__device__ float    g_xqt[NLAT_IN * NLON_IN * BC];       // 33.4 MB
__device__ float    g_wt[CK * COUT];                     // W transposed [ck][o]
__device__ int2     g_ent[MAX_NNZ];                      // (k<<12|cell, psi_bits)
__device__ int      g_he[NLAT_OUT + 1];                  // per-h entry ranges
__device__ float    g_psi[(NLAT_OUT * NCELL + 4) * RECF]; // records (hdr fused)
__device__ int      g_npix[NLAT_OUT];

// ---------------- 1) decode entries + per-h ranges ----------------
// dtype: word pidx32[2*nnz-1] is h_last=90 (int32) or high half of flat (=0, int64)
__global__ void decode_kernel(const int* __restrict__ pidx,
                              const float* __restrict__ pvals, int nnz) {
    int e = blockIdx.x * blockDim.x + threadIdx.x;
    if (e >= nnz || e >= MAX_NNZ) return;
    int is64 = (pidx[2 * nnz - 1] == 0) ? 1 : 0;
    int k, h, flat, hp = -1;
    if (is64) {
        const long long* p = (const long long*)pidx;
        k = (int)p[e]; h = (int)p[(long long)nnz + e]; flat = (int)p[2LL * nnz + e];
        if (e > 0) hp = (int)p[(long long)nnz + e - 1];
    } else {
        k = pidx[e]; h = pidx[nnz + e]; flat = pidx[2 * nnz + e];
        if (e > 0) hp = pidx[nnz + e - 1];
    }
    int row = flat / NLON_IN;
    int lon = flat - row * NLON_IN;
    int row0 = 2 * h - 4; if (row0 < 0) row0 = 0;
    int rr = row - row0;
    rr = rr < 0 ? 0 : (rr > 8 ? 8 : rr);             // safety clamp (data guarantees 0..8)
    int2 ent;
    ent.x = ((k & 15) << 12) | (rr * NLON_IN + lon);
    ent.y = __float_as_int(pvals[e]);
    g_ent[e] = ent;

    for (int t = hp + 1; t <= h; t++) g_he[t] = e;   // h is ascending
    if (e == nnz - 1)
        for (int t = h + 1; t <= NLAT_OUT; t++) g_he[t] = nnz;
}

// ---------------- 2) per-h build: count -> scan -> zero -> scatter ----------------
__global__ void __launch_bounds__(1024) build_kernel() {
    __shared__ int s_cnt[NCELL];                     // 12.96 KB (count -> slot map)
    __shared__ int s_wf[32];
    __shared__ int s_pixb;
    int h = blockIdx.x;
    int t = threadIdx.x, lane = t & 31, wid = t >> 5;
    int row0 = 2 * h - 4; if (row0 < 0) row0 = 0;

    for (int c = t; c < NCELL; c += 1024) s_cnt[c] = 0;
    if (t == 0) s_pixb = 0;
    __syncthreads();

    int e0 = g_he[h], e1 = g_he[h + 1];
    for (int e = e0 + t; e < e1; e += 1024)
        atomicAdd(&s_cnt[g_ent[e].x & 4095], 1);
    __syncthreads();

    float* psi = g_psi + (size_t)h * NCELL * RECF;

    // chunked block scan over 3240 cells: compact slot ids
    for (int c0 = 0; c0 < NCELL; c0 += 1024) {
        int cell = c0 + t;
        int flag = (cell < NCELL && s_cnt[cell] > 0) ? 1 : 0;
        int sf = flag;
        #pragma unroll
        for (int o = 1; o < 32; o <<= 1) {
            int vf = __shfl_up_sync(~0u, sf, o);
            if (lane >= o) sf += vf;
        }
        if (lane == 31) s_wf[wid] = sf;
        __syncthreads();
        if (wid == 0) {
            int wf = s_wf[lane];
            #pragma unroll
            for (int o = 1; o < 32; o <<= 1) {
                int vf = __shfl_up_sync(~0u, wf, o);
                if (lane >= o) wf += vf;
            }
            s_wf[lane] = wf;
        }
        __syncthreads();
        int exf = sf - flag + ((wid > 0) ? s_wf[wid - 1] : 0);
        int pixb = s_pixb;
        if (flag) s_cnt[cell] = pixb + exf;          // slot map
        __syncthreads();
        if (t == 0) s_pixb += s_wf[31];
        __syncthreads();
    }
    int np = s_pixb;
    if (t == 0) g_npix[h] = np;

    // zero np records
    for (int i = t; i < np * RECF; i += 1024) psi[i] = 0.f;
    __syncthreads();

    // scatter psi + fused header (idempotent) into dense records
    for (int e = e0 + t; e < e1; e += 1024) {
        int2 ent = g_ent[e];
        int cell = ent.x & 4095;
        int k    = (ent.x >> 12) & 15;
        int slot = s_cnt[cell];
        psi[slot * RECF + k] = __int_as_float(ent.y);
        int rr  = cell / NLON_IN;
        int lon = cell - rr * NLON_IN;
        int rowbase = (row0 + rr) * NLON_IN;
        psi[slot * RECF + 9] =
            __uint_as_float(((uint32_t)rowbase << 9) | (uint32_t)lon);
    }
}

// ---------------- 3) fused xq-transpose + W-transpose ----------------
__global__ void __launch_bounds__(256) xqwt_kernel(const float* __restrict__ x,
                                                   const float* __restrict__ qw,
                                                   const float* __restrict__ w) {
    int bi = blockIdx.x;
    if (bi < 8688) {
        __shared__ float tile[32][33];
        int g0 = bi % 12, g1 = (bi / 12) % 4, row = bi / 48;
        int lon0 = g0 * 32, bc0 = g1 * 32;
        int tx = threadIdx.x & 31, ty = threadIdx.x >> 5;   // 32 x 8
        float q = qw[row];
        for (int i = ty; i < 32; i += 8) {
            int lon = lon0 + tx;
            float v = 0.f;
            if (lon < NLON_IN)
                v = x[((size_t)(bc0 + i) * NLAT_IN + row) * NLON_IN + lon];
            tile[i][tx] = v * q;
        }
        __syncthreads();
        for (int i = ty; i < 32; i += 8) {
            int lon = lon0 + i;
            if (lon < NLON_IN)
                g_xqt[((size_t)(row * NLON_IN + lon)) * BC + bc0 + tx] = tile[tx][i];
        }
    } else {
        int id = (bi - 8688) * 256 + threadIdx.x;
        if (id < COUT * CK) {
            int o = id / CK;
            int ck = id - o * CK;
            g_wt[ck * COUT + o] = w[id];
        }
    }
}

// ---------------- 4) fused conv: split-channel warps (high occupancy) ----------------
__global__ void __launch_bounds__(320, 4) conv_kernel(const float* __restrict__ bias,
                                                      float* __restrict__ out) {
    __shared__ float s_acc[WT * 4 * 289];            // 20 slots x 289 = 23.1 KB

    int wt = blockIdx.x;
    int u  = blockIdx.y;
    int h  = (u & 1) ? (90 - (u >> 1)) : (u >> 1);   // heavy polar rows first
    int lane = threadIdx.x & 31;
    int warp = threadIdx.x >> 5;                     // 10 warps
    int wl    = warp >> 1;                           // 0..4 local longitude
    int chalf = warp & 1;                            // 0/1 channel half
    int w = wt * WT + wl;
    int tw = 2 * w;
    int vbase = chalf * 64 + lane * 2;               // this lane's 2 channels (bc, bc+1)

    int np = g_npix[h];
    const float4* __restrict__ rec = (const float4*)(g_psi + (size_t)h * NCELL * RECF);

    float y0[KS], y1[KS];                            // 18 accumulators
    #pragma unroll
    for (int k = 0; k < KS; k++) { y0[k] = 0.f; y1[k] = 0.f; }

    #pragma unroll 2
    for (int p = 0; p < np; p++) {
        float4 q0 = __ldg(&rec[p * 3 + 0]);
        float4 q1 = __ldg(&rec[p * 3 + 1]);
        float4 q2 = __ldg(&rec[p * 3 + 2]);
        uint32_t hd = __float_as_uint(q2.y);
        int col = (int)(hd & 511) + tw; if (col >= NLON_IN) col -= NLON_IN;
        float2 v = __ldg((const float2*)&g_xqt[((size_t)((hd >> 9) + col)) * BC + vbase]);
        y0[0] = fmaf(q0.x, v.x, y0[0]);  y1[0] = fmaf(q0.x, v.y, y1[0]);
        y0[1] = fmaf(q0.y, v.x, y0[1]);  y1[1] = fmaf(q0.y, v.y, y1[1]);
        y0[2] = fmaf(q0.z, v.x, y0[2]);  y1[2] = fmaf(q0.z, v.y, y1[2]);
        y0[3] = fmaf(q0.w, v.x, y0[3]);  y1[3] = fmaf(q0.w, v.y, y1[3]);
        y0[4] = fmaf(q1.x, v.x, y0[4]);  y1[4] = fmaf(q1.x, v.y, y1[4]);
        y0[5] = fmaf(q1.y, v.x, y0[5]);  y1[5] = fmaf(q1.y, v.y, y1[5]);
        y0[6] = fmaf(q1.z, v.x, y0[6]);  y1[6] = fmaf(q1.z, v.y, y1[6]);
        y0[7] = fmaf(q1.w, v.x, y0[7]);  y1[7] = fmaf(q1.w, v.y, y1[7]);
        y0[8] = fmaf(q2.x, v.x, y0[8]);  y1[8] = fmaf(q2.x, v.y, y1[8]);
    }

    // stage-1 result -> smem [wl*4 + b][c*9 + k]   (bc = chalf*64 + lane*2)
    {
        int bc = vbase;
        int b0 = bc >> 5, c0 = bc & 31;              // second channel: bc+1 (same b)
        int sb = (wl * 4 + b0) * 289 + c0 * KS;
        #pragma unroll
        for (int k = 0; k < KS; k++) {
            s_acc[sb + k]      = y0[k];
            s_acc[sb + KS + k] = y1[k];
        }
    }
    __syncthreads();

    // stage 2: out[b,o,h,w] = sum_ck W[o][ck] * y[b][ck] ; lane = o, 2 slots per warp
    int slotA = warp * 2, slotB = warp * 2 + 1;
    const float* sA = &s_acc[slotA * 289];
    const float* sB = &s_acc[slotB * 289];
    float rA = 0.f, rB = 0.f;
    #pragma unroll 4
    for (int ck = 0; ck < CK; ck++) {
        float wv = g_wt[ck * COUT + lane];
        rA = fmaf(wv, sA[ck], rA);
        rB = fmaf(wv, sB[ck], rB);
    }
    float bo = bias[lane];
    {
        int wpA = slotA >> 2, bpA = slotA & 3;
        int wpB = slotB >> 2, bpB = slotB & 3;
        out[(((size_t)(bpA * COUT + lane)) * NLAT_OUT + h) * NLON_OUT + (wt * WT + wpA)]
            = rA + bo;
        out[(((size_t)(bpB * COUT + lane)) * NLAT_OUT + h) * NLON_OUT + (wt * WT + wpB)]
            = rB + bo;
    }
}

// ---------------- launch ----------------
extern "C" void kernel_launch(void* const* d_in, const int* in_sizes, int n_in,
                              void* d_out, int out_size) {
    const float* x      = (const float*)d_in[0];
    const float* qw     = (const float*)d_in[1];
    const float* pvals  = (const float*)d_in[2];
    const float* weight = (const float*)d_in[3];
    const float* bias   = (const float*)d_in[4];
    const int*   pidx   = (const int*)d_in[5];
    float* out = (float*)d_out;

    int nnz = in_sizes[2];

    cudaFuncSetAttribute(conv_kernel,
                         cudaFuncAttributePreferredSharedMemoryCarveout,
                         cudaSharedmemCarveoutMaxShared);

    decode_kernel<<<(nnz + 255) / 256, 256>>>(pidx, pvals, nnz);        // launch 1
    build_kernel<<<NLAT_OUT, 1024>>>();                                 // launch 2
    xqwt_kernel<<<8724, 256>>>(x, qw, weight);                          // launch 3
    conv_kernel<<<dim3(NWTILES, NLAT_OUT), 320>>>(bias, out);           // launch 4 (profiled)
}

// round 12
// speedup vs baseline: 1.5065x; 1.0028x over previous
#include <cuda_runtime.h>
#include <stdint.h>

// Problem constants (fixed by the dataset)
#define NLAT_IN  181
#define NLON_IN  360
#define NLAT_OUT 91
#define NLON_OUT 180
#define KS       9
#define B_       4
#define CIN      32
#define COUT     32
#define BC       128
#define CK       288                     // CIN*KS

#define WT       5                       // longitudes per block (5 w x 2 chalf = 10 warps)
#define NWTILES  (NLON_OUT / WT)         // 36

#define MAX_NNZ   (1 << 21)
#define NCELL     (9 * NLON_IN)          // 3240 (rr, lon) cells per output lat
#define RECF      12                     // floats per record: psi[0..8], hdr, pad, pad

// ---------------- device scratch (no cudaMalloc allowed) ----------------
__device__ float    g_xqt[NLAT_IN * NLON_IN * BC];       // 33.4 MB
__device__ float    g_wt[CK * COUT];                     // W transposed [ck][o]
__device__ int2     g_ent[MAX_NNZ];                      // (k<<12|cell, psi_bits)
__device__ int      g_he[NLAT_OUT + 1];                  // per-h entry ranges
__device__ float    g_psi[(NLAT_OUT * NCELL + 4) * RECF]; // records (hdr fused)
__device__ int      g_npix[NLAT_OUT];

// ---------------- 1) decode entries + per-h ranges ----------------
// dtype: word pidx32[2*nnz-1] is h_last=90 (int32) or high half of flat (=0, int64)
__global__ void decode_kernel(const int* __restrict__ pidx,
                              const float* __restrict__ pvals, int nnz) {
    int e = blockIdx.x * blockDim.x + threadIdx.x;
    if (e >= nnz || e >= MAX_NNZ) return;
    int is64 = (pidx[2 * nnz - 1] == 0) ? 1 : 0;
    int k, h, flat, hp = -1;
    if (is64) {
        const long long* p = (const long long*)pidx;
        k = (int)p[e]; h = (int)p[(long long)nnz + e]; flat = (int)p[2LL * nnz + e];
        if (e > 0) hp = (int)p[(long long)nnz + e - 1];
    } else {
        k = pidx[e]; h = pidx[nnz + e]; flat = pidx[2 * nnz + e];
        if (e > 0) hp = pidx[nnz + e - 1];
    }
    int row = flat / NLON_IN;
    int lon = flat - row * NLON_IN;
    int row0 = 2 * h - 4; if (row0 < 0) row0 = 0;
    int rr = row - row0;
    rr = rr < 0 ? 0 : (rr > 8 ? 8 : rr);             // safety clamp (data guarantees 0..8)
    int2 ent;
    ent.x = ((k & 15) << 12) | (rr * NLON_IN + lon);
    ent.y = __float_as_int(pvals[e]);
    g_ent[e] = ent;

    for (int t = hp + 1; t <= h; t++) g_he[t] = e;   // h is ascending
    if (e == nnz - 1)
        for (int t = h + 1; t <= NLAT_OUT; t++) g_he[t] = nnz;
}

// ---------------- 2) per-h build: count -> scan -> zero -> scatter ----------------
__global__ void __launch_bounds__(1024) build_kernel() {
    __shared__ int s_cnt[NCELL];                     // 12.96 KB (count -> slot map)
    __shared__ int s_wf[32];
    __shared__ int s_pixb;
    int h = blockIdx.x;
    int t = threadIdx.x, lane = t & 31, wid = t >> 5;
    int row0 = 2 * h - 4; if (row0 < 0) row0 = 0;

    for (int c = t; c < NCELL; c += 1024) s_cnt[c] = 0;
    if (t == 0) s_pixb = 0;
    __syncthreads();

    int e0 = g_he[h], e1 = g_he[h + 1];
    for (int e = e0 + t; e < e1; e += 1024)
        atomicAdd(&s_cnt[g_ent[e].x & 4095], 1);
    __syncthreads();

    float* psi = g_psi + (size_t)h * NCELL * RECF;

    // chunked block scan over 3240 cells: compact slot ids
    for (int c0 = 0; c0 < NCELL; c0 += 1024) {
        int cell = c0 + t;
        int flag = (cell < NCELL && s_cnt[cell] > 0) ? 1 : 0;
        int sf = flag;
        #pragma unroll
        for (int o = 1; o < 32; o <<= 1) {
            int vf = __shfl_up_sync(~0u, sf, o);
            if (lane >= o) sf += vf;
        }
        if (lane == 31) s_wf[wid] = sf;
        __syncthreads();
        if (wid == 0) {
            int wf = s_wf[lane];
            #pragma unroll
            for (int o = 1; o < 32; o <<= 1) {
                int vf = __shfl_up_sync(~0u, wf, o);
                if (lane >= o) wf += vf;
            }
            s_wf[lane] = wf;
        }
        __syncthreads();
        int exf = sf - flag + ((wid > 0) ? s_wf[wid - 1] : 0);
        int pixb = s_pixb;
        if (flag) s_cnt[cell] = pixb + exf;          // slot map
        __syncthreads();
        if (t == 0) s_pixb += s_wf[31];
        __syncthreads();
    }
    int np = s_pixb;
    if (t == 0) g_npix[h] = np;

    // zero np records
    for (int i = t; i < np * RECF; i += 1024) psi[i] = 0.f;
    __syncthreads();

    // scatter psi + fused header (idempotent) into dense records
    for (int e = e0 + t; e < e1; e += 1024) {
        int2 ent = g_ent[e];
        int cell = ent.x & 4095;
        int k    = (ent.x >> 12) & 15;
        int slot = s_cnt[cell];
        psi[slot * RECF + k] = __int_as_float(ent.y);
        int rr  = cell / NLON_IN;
        int lon = cell - rr * NLON_IN;
        int rowbase = (row0 + rr) * NLON_IN;
        psi[slot * RECF + 9] =
            __uint_as_float(((uint32_t)rowbase << 9) | (uint32_t)lon);
    }
}

// ---------------- 3) fused xq-transpose + W-transpose ----------------
__global__ void __launch_bounds__(256) xqwt_kernel(const float* __restrict__ x,
                                                   const float* __restrict__ qw,
                                                   const float* __restrict__ w) {
    int bi = blockIdx.x;
    if (bi < 8688) {
        __shared__ float tile[32][33];
        int g0 = bi % 12, g1 = (bi / 12) % 4, row = bi / 48;
        int lon0 = g0 * 32, bc0 = g1 * 32;
        int tx = threadIdx.x & 31, ty = threadIdx.x >> 5;   // 32 x 8
        float q = qw[row];
        for (int i = ty; i < 32; i += 8) {
            int lon = lon0 + tx;
            float v = 0.f;
            if (lon < NLON_IN)
                v = x[((size_t)(bc0 + i) * NLAT_IN + row) * NLON_IN + lon];
            tile[i][tx] = v * q;
        }
        __syncthreads();
        for (int i = ty; i < 32; i += 8) {
            int lon = lon0 + i;
            if (lon < NLON_IN)
                g_xqt[((size_t)(row * NLON_IN + lon)) * BC + bc0 + tx] = tile[tx][i];
        }
    } else {
        int id = (bi - 8688) * 256 + threadIdx.x;
        if (id < COUT * CK) {
            int o = id / CK;
            int ck = id - o * CK;
            g_wt[ck * COUT + o] = w[id];
        }
    }
}

// ---------------- 4) fused conv: split-channel warps (high occupancy) ----------------
__global__ void __launch_bounds__(320, 4) conv_kernel(const float* __restrict__ bias,
                                                      float* __restrict__ out) {
    __shared__ float s_acc[WT * 4 * 289];            // 20 slots x 289 = 23.1 KB

    int wt = blockIdx.x;
    int u  = blockIdx.y;
    int h  = (u & 1) ? (90 - (u >> 1)) : (u >> 1);   // heavy polar rows first
    int lane = threadIdx.x & 31;
    int warp = threadIdx.x >> 5;                     // 10 warps
    int wl    = warp >> 1;                           // 0..4 local longitude
    int chalf = warp & 1;                            // 0/1 channel half
    int w = wt * WT + wl;
    int tw = 2 * w;
    int vbase = chalf * 64 + lane * 2;               // this lane's 2 channels (bc, bc+1)

    int np = g_npix[h];
    const float4* __restrict__ rec = (const float4*)(g_psi + (size_t)h * NCELL * RECF);

    float y0[KS], y1[KS];                            // 18 accumulators
    #pragma unroll
    for (int k = 0; k < KS; k++) { y0[k] = 0.f; y1[k] = 0.f; }

    #pragma unroll 2
    for (int p = 0; p < np; p++) {
        float4 q0 = __ldg(&rec[p * 3 + 0]);
        float4 q1 = __ldg(&rec[p * 3 + 1]);
        float4 q2 = __ldg(&rec[p * 3 + 2]);
        uint32_t hd = __float_as_uint(q2.y);
        int col = (int)(hd & 511) + tw; if (col >= NLON_IN) col -= NLON_IN;
        float2 v = __ldg((const float2*)&g_xqt[((size_t)((hd >> 9) + col)) * BC + vbase]);
        y0[0] = fmaf(q0.x, v.x, y0[0]);  y1[0] = fmaf(q0.x, v.y, y1[0]);
        y0[1] = fmaf(q0.y, v.x, y0[1]);  y1[1] = fmaf(q0.y, v.y, y1[1]);
        y0[2] = fmaf(q0.z, v.x, y0[2]);  y1[2] = fmaf(q0.z, v.y, y1[2]);
        y0[3] = fmaf(q0.w, v.x, y0[3]);  y1[3] = fmaf(q0.w, v.y, y1[3]);
        y0[4] = fmaf(q1.x, v.x, y0[4]);  y1[4] = fmaf(q1.x, v.y, y1[4]);
        y0[5] = fmaf(q1.y, v.x, y0[5]);  y1[5] = fmaf(q1.y, v.y, y1[5]);
        y0[6] = fmaf(q1.z, v.x, y0[6]);  y1[6] = fmaf(q1.z, v.y, y1[6]);
        y0[7] = fmaf(q1.w, v.x, y0[7]);  y1[7] = fmaf(q1.w, v.y, y1[7]);
        y0[8] = fmaf(q2.x, v.x, y0[8]);  y1[8] = fmaf(q2.x, v.y, y1[8]);
    }

    // stage-1 result -> smem [wl*4 + b][c*9 + k]   (bc = chalf*64 + lane*2)
    {
        int bc = vbase;
        int b0 = bc >> 5, c0 = bc & 31;              // second channel: bc+1 (same b)
        int sb = (wl * 4 + b0) * 289 + c0 * KS;
        #pragma unroll
        for (int k = 0; k < KS; k++) {
            s_acc[sb + k]      = y0[k];
            s_acc[sb + KS + k] = y1[k];
        }
    }
    __syncthreads();

    // stage 2: out[b,o,h,w] = sum_ck W[o][ck] * y[b][ck] ; lane = o, 2 slots per warp
    int slotA = warp * 2, slotB = warp * 2 + 1;
    const float* sA = &s_acc[slotA * 289];
    const float* sB = &s_acc[slotB * 289];
    float rA = 0.f, rB = 0.f;
    #pragma unroll 4
    for (int ck = 0; ck < CK; ck++) {
        float wv = g_wt[ck * COUT + lane];
        rA = fmaf(wv, sA[ck], rA);
        rB = fmaf(wv, sB[ck], rB);
    }
    float bo = bias[lane];
    {
        int wpA = slotA >> 2, bpA = slotA & 3;
        int wpB = slotB >> 2, bpB = slotB & 3;
        out[(((size_t)(bpA * COUT + lane)) * NLAT_OUT + h) * NLON_OUT + (wt * WT + wpA)]
            = rA + bo;
        out[(((size_t)(bpB * COUT + lane)) * NLAT_OUT + h) * NLON_OUT + (wt * WT + wpB)]
            = rB + bo;
    }
}

// ---------------- launch ----------------
extern "C" void kernel_launch(void* const* d_in, const int* in_sizes, int n_in,
                              void* d_out, int out_size) {
    const float* x      = (const float*)d_in[0];
    const float* qw     = (const float*)d_in[1];
    const float* pvals  = (const float*)d_in[2];
    const float* weight = (const float*)d_in[3];
    const float* bias   = (const float*)d_in[4];
    const int*   pidx   = (const int*)d_in[5];
    float* out = (float*)d_out;

    int nnz = in_sizes[2];

    cudaFuncSetAttribute(conv_kernel,
                         cudaFuncAttributePreferredSharedMemoryCarveout,
                         cudaSharedmemCarveoutMaxShared);

    decode_kernel<<<(nnz + 255) / 256, 256>>>(pidx, pvals, nnz);        // launch 1
    build_kernel<<<NLAT_OUT, 1024>>>();                                 // launch 2
    xqwt_kernel<<<8724, 256>>>(x, qw, weight);                          // launch 3
    conv_kernel<<<dim3(NWTILES, NLAT_OUT), 320>>>(bias, out);           // launch 4 (profiled)
}